// round 1
// baseline (speedup 1.0000x reference)
#include <cuda_runtime.h>

namespace {
constexpr int N_COLS = 8192;   // row length (fixed by problem)
constexpr int W_MAX  = 15;     // widths w = 2..15
constexpr int NW     = 14;     // number of widths
constexpr int HALO   = 14;     // W_MAX - 1
constexpr int TPB    = 256;
constexpr int K_TOK  = 16;     // tokens per thread (consecutive)
constexpr int TILE   = TPB * K_TOK;   // 4096 tokens per CTA
constexpr float NEGV = -1.0e9f;
}

__global__ __launch_bounds__(TPB) void span_boost_kernel(
    const float* __restrict__ scores,
    const int*   __restrict__ mask,
    const float* __restrict__ gamma_p,
    const float* __restrict__ wlog,
    float*       __restrict__ out)
{
    __shared__ float sv[TILE + 2 * HALO];
    __shared__ float sww[NW];

    const float NINF = __int_as_float(0xff800000);  // -inf sentinel: excludes
                                                    // windows crossing row edges
    const int row  = blockIdx.y;
    const int col0 = blockIdx.x * TILE;
    const float* srow = scores + (size_t)row * N_COLS;
    const int*   mrow = mask   + (size_t)row * N_COLS;

    // ---- stage masked tile (+halo) into smem, coalesced ----
    for (int i = threadIdx.x; i < TILE + 2 * HALO; i += TPB) {
        int g = col0 - HALO + i;
        float v = NINF;
        if (g >= 0 && g < N_COLS) {
            float s = srow[g];
            v = (mrow[g] == 0) ? NEGV : s;
        }
        sv[i] = v;
    }

    // ---- softmax of width logits (once per CTA; W=15 trivial) ----
    if (threadIdx.x == 0) {
        float mx = wlog[0];
        #pragma unroll
        for (int j = 1; j < W_MAX; j++) mx = fmaxf(mx, wlog[j]);
        float e[W_MAX];
        float ssum = 0.f;
        #pragma unroll
        for (int j = 0; j < W_MAX; j++) { e[j] = expf(wlog[j] - mx); ssum += e[j]; }
        float inv = 1.f / ssum;
        #pragma unroll
        for (int j = 0; j < NW; j++) sww[j] = e[j] * inv;  // only w=2..15 used
    }
    __syncthreads();

    float ww[NW];
    #pragma unroll
    for (int j = 0; j < NW; j++) ww[j] = sww[j];

    // ---- register-stage 44 values: positions [t0-14 .. t0+K-1+14] ----
    // base is a multiple of 16 words -> LDS.128 aligned
    const int base = threadIdx.x * K_TOK;
    float r[K_TOK + 2 * HALO];
    #pragma unroll
    for (int q = 0; q < (K_TOK + 2 * HALO) / 4; q++) {
        float4 f = *reinterpret_cast<const float4*>(&sv[base + 4 * q]);
        r[4*q+0] = f.x; r[4*q+1] = f.y; r[4*q+2] = f.z; r[4*q+3] = f.w;
    }

    float boost[K_TOK];
    #pragma unroll
    for (int t = 0; t < K_TOK; t++) boost[t] = NINF;

    // ---- per window-start: incremental window-min, weighted, suffix-max
    //      scatter. Position j corresponds to start s = t0 - 14 + j.
    //      Token index hit by depth d (w >= d needed): ti = j + d - 15.
    //      All ti bounds are compile-time under full unroll -> dead updates
    //      are pruned, no runtime predication. ----
    #pragma unroll
    for (int j = 0; j < K_TOK + HALO; j++) {
        float mm[NW];
        float m = fminf(r[j], r[j + 1]);      // w = 2
        mm[0] = m;
        #pragma unroll
        for (int w = 3; w <= W_MAX; w++) {    // w = 3..15 incremental
            m = fminf(m, r[j + w - 1]);
            mm[w - 2] = m;
        }
        float g = ww[NW - 1] * mm[NW - 1];    // d = 15 : G_15 = h_15
        if (j < K_TOK) boost[j] = fmaxf(boost[j], g);
        #pragma unroll
        for (int d = W_MAX - 1; d >= 2; d--) {  // d = 14..2 suffix max
            g = fmaxf(g, ww[d - 2] * mm[d - 2]);
            const int ti = j + d - W_MAX;
            if (ti >= 0 && ti < K_TOK) boost[ti] = fmaxf(boost[ti], g);
        }
        {   // d = 1 shares G_2 (w >= max(1,2))
            const int ti = j + 1 - W_MAX;
            if (ti >= 0 && ti < K_TOK) boost[ti] = fmaxf(boost[ti], g);
        }
    }

    // ---- epilogue: out = score + gamma * max(boost, masked), float4 ----
    const float gamma = *gamma_p;
    const int tcol = col0 + base;
    float* orow = out + (size_t)row * N_COLS;
    #pragma unroll
    for (int q = 0; q < K_TOK / 4; q++) {
        float4 s4 = *reinterpret_cast<const float4*>(&srow[tcol + 4 * q]);
        float4 o;
        o.x = s4.x + gamma * fmaxf(boost[4*q+0], r[4*q+0 + HALO]);
        o.y = s4.y + gamma * fmaxf(boost[4*q+1], r[4*q+1 + HALO]);
        o.z = s4.z + gamma * fmaxf(boost[4*q+2], r[4*q+2 + HALO]);
        o.w = s4.w + gamma * fmaxf(boost[4*q+3], r[4*q+3 + HALO]);
        *reinterpret_cast<float4*>(&orow[tcol + 4 * q]) = o;
    }
}

extern "C" void kernel_launch(void* const* d_in, const int* in_sizes, int n_in,
                              void* d_out, int out_size)
{
    const float* scores = (const float*)d_in[0];
    const int*   mask   = (const int*)d_in[1];
    const float* gamma  = (const float*)d_in[2];
    const float* wlog   = (const float*)d_in[3];
    float* out = (float*)d_out;
    const int B = in_sizes[0] / N_COLS;   // 512
    dim3 grid(N_COLS / TILE, B);          // (2, 512)
    span_boost_kernel<<<grid, TPB>>>(scores, mask, gamma, wlog, out);
}

// round 2
// speedup vs baseline: 1.1758x; 1.1758x over previous
#include <cuda_runtime.h>

namespace {
constexpr int N_COLS = 8192;   // row length (fixed by problem)
constexpr int W_MAX  = 15;     // widths w = 2..15
constexpr int NW     = 14;
constexpr int HALO   = 14;     // W_MAX - 1
constexpr int TPB    = 128;
constexpr int K_TOK  = 16;     // tokens per thread
constexpr int TILE   = TPB * K_TOK;        // 2048
constexpr int LPAD   = 16;                 // left pad in sv (>= HALO, 16-aligned)
constexpr int SV_LEN = TILE + LPAD + HALO; // 2078
constexpr int SV_PAD = 2080;               // rounded to /4
constexpr float NEGV = -1.0e9f;
constexpr unsigned KEY_NINF = 0x007fffffu; // fkey(-inf)
}

// order-preserving float<->uint key (total order, works for -inf)
__device__ __forceinline__ unsigned fkey(float f) {
    int u = __float_as_int(f);
    return (u >= 0) ? ((unsigned)u | 0x80000000u) : ~(unsigned)u;
}
__device__ __forceinline__ float funkey(unsigned k) {
    unsigned u = (k & 0x80000000u) ? (k & 0x7fffffffu) : ~k;
    return __int_as_float((int)u);
}

__global__ __launch_bounds__(TPB, 5) void span_boost_kernel(
    const float* __restrict__ scores,
    const int*   __restrict__ mask,
    const float* __restrict__ gamma_p,
    const float* __restrict__ wlog,
    float*       __restrict__ out)
{
    __shared__ float    sv[SV_PAD];        // masked values, sv[i] = token col0-LPAD+i
    __shared__ float    sww[NW];
    __shared__ unsigned xb[HALO];          // CTA-left-halo boost (int-keyed max)
    __shared__ float    tailbuf[TPB][15];  // stride 15: conflict-free

    const float NINF = __int_as_float(0xff800000);
    const int   tid  = threadIdx.x;
    const int   row  = blockIdx.y;
    const int   col0 = blockIdx.x * TILE;
    const float* srow = scores + (size_t)row * N_COLS;
    const int*   mrow = mask   + (size_t)row * N_COLS;
    const int base_g = col0 - LPAD;        // global token index of sv[0]

    // ---- stage masked tile (vectorized; scalar fallback at row edges) ----
    for (int i = tid * 4; i < SV_PAD; i += TPB * 4) {
        int g = base_g + i;                // ≡ 0 (mod 4) -> aligned
        float4 v;
        if (g >= 0 && g + 3 < N_COLS) {
            float4 s4 = *reinterpret_cast<const float4*>(srow + g);
            int4   m4 = *reinterpret_cast<const int4*>(mrow + g);
            v.x = (m4.x == 0) ? NEGV : s4.x;
            v.y = (m4.y == 0) ? NEGV : s4.y;
            v.z = (m4.z == 0) ? NEGV : s4.z;
            v.w = (m4.w == 0) ? NEGV : s4.w;
        } else {
            float t[4];
            #pragma unroll
            for (int k = 0; k < 4; k++) {
                int gg = g + k;
                t[k] = (gg >= 0 && gg < N_COLS)
                         ? ((mrow[gg] == 0) ? NEGV : srow[gg]) : NINF;
            }
            v.x = t[0]; v.y = t[1]; v.z = t[2]; v.w = t[3];
        }
        *reinterpret_cast<float4*>(sv + i) = v;
    }
    if (tid < HALO) xb[tid] = KEY_NINF;
    if (tid == 0) {  // softmax over 15 width logits
        float mx = wlog[0];
        #pragma unroll
        for (int j = 1; j < W_MAX; j++) mx = fmaxf(mx, wlog[j]);
        float e[W_MAX], ssum = 0.f;
        #pragma unroll
        for (int j = 0; j < W_MAX; j++) { e[j] = expf(wlog[j] - mx); ssum += e[j]; }
        float inv = 1.f / ssum;
        #pragma unroll
        for (int j = 0; j < NW; j++) sww[j] = e[j + 1] * inv;  // widths 2..15
    }
    __syncthreads();

    float ww[NW];
    #pragma unroll
    for (int j = 0; j < NW; j++) ww[j] = sww[j];

    // ---- register-stage r[0..29]: sv[base .. base+29] (base 16-aligned) ----
    const int base = LPAD + tid * K_TOK;
    float r[K_TOK + HALO];
    #pragma unroll
    for (int q = 0; q < 7; q++) {
        float4 f = *reinterpret_cast<const float4*>(&sv[base + 4 * q]);
        r[4*q+0] = f.x; r[4*q+1] = f.y; r[4*q+2] = f.z; r[4*q+3] = f.w;
    }
    r[28] = sv[base + 28];
    r[29] = sv[base + 29];

    float boost[K_TOK + HALO];
    #pragma unroll
    for (int t = 0; t < K_TOK + HALO; t++) boost[t] = NINF;

    // ---- own 16 starts: incremental window-min, suffix-max scatter ----
    // start j (token t0+j); depth d hits local token j+d-1.
    #pragma unroll
    for (int j = 0; j < K_TOK; j++) {
        float mm[NW];
        float m = fminf(r[j], r[j + 1]);
        mm[0] = m;
        #pragma unroll
        for (int w = 3; w <= W_MAX; w++) { m = fminf(m, r[j + w - 1]); mm[w - 2] = m; }
        float g = ww[NW - 1] * mm[NW - 1];
        boost[j + 14] = fmaxf(boost[j + 14], g);            // d = 15
        #pragma unroll
        for (int d = W_MAX - 1; d >= 2; d--) {              // d = 14..2
            g = fmaxf(g, ww[d - 2] * mm[d - 2]);
            boost[j + d - 1] = fmaxf(boost[j + d - 1], g);
        }
        boost[j] = fmaxf(boost[j], g);                      // d = 1 shares G(s,2)
    }

    // ---- export tail (tokens 16..29 -> next thread's tokens 0..13) ----
    #pragma unroll
    for (int k = 0; k < HALO; k++) tailbuf[tid][k] = boost[K_TOK + k];

    // ---- CTA-left halo starts: threads 0..13 compute start col0-14+h ----
    if (tid < HALO) {
        const int h = tid;                 // sv index of start: h + 2
        float mm[NW];
        float m = fminf(sv[h + 2], sv[h + 3]);
        mm[0] = m;
        #pragma unroll
        for (int w = 3; w <= W_MAX; w++) { m = fminf(m, sv[h + 1 + w]); mm[w - 2] = m; }
        float g = ww[NW - 1] * mm[NW - 1];
        atomicMax(&xb[h], fkey(g));        // d = 15 -> token h
        #pragma unroll
        for (int d = W_MAX - 1; d >= 2; d--) {
            g = fmaxf(g, ww[d - 2] * mm[d - 2]);
            int i = h + d - W_MAX;         // token index in [0,14)
            if (i >= 0) atomicMax(&xb[i], fkey(g));
        }
        // d = 1 -> i = h-14 < 0 always: previous CTA's token, skip
    }
    __syncthreads();

    // ---- merge incoming contributions into tokens 0..13 ----
    if (tid > 0) {
        #pragma unroll
        for (int k = 0; k < HALO; k++)
            boost[k] = fmaxf(boost[k], tailbuf[tid - 1][k]);
    } else {
        #pragma unroll
        for (int k = 0; k < HALO; k++)
            boost[k] = fmaxf(boost[k], funkey(xb[k]));
    }

    // ---- epilogue: out = score + gamma * max(boost, masked) ----
    const float gamma = *gamma_p;
    const int tcol = col0 + tid * K_TOK;
    float* orow = out + (size_t)row * N_COLS;
    #pragma unroll
    for (int q = 0; q < K_TOK / 4; q++) {
        float4 s4 = *reinterpret_cast<const float4*>(&srow[tcol + 4 * q]);
        float4 o;
        o.x = s4.x + gamma * fmaxf(boost[4*q+0], r[4*q+0]);
        o.y = s4.y + gamma * fmaxf(boost[4*q+1], r[4*q+1]);
        o.z = s4.z + gamma * fmaxf(boost[4*q+2], r[4*q+2]);
        o.w = s4.w + gamma * fmaxf(boost[4*q+3], r[4*q+3]);
        *reinterpret_cast<float4*>(&orow[tcol + 4 * q]) = o;
    }
}

extern "C" void kernel_launch(void* const* d_in, const int* in_sizes, int n_in,
                              void* d_out, int out_size)
{
    const float* scores = (const float*)d_in[0];
    const int*   mask   = (const int*)d_in[1];
    const float* gamma  = (const float*)d_in[2];
    const float* wlog   = (const float*)d_in[3];
    float* out = (float*)d_out;
    const int B = in_sizes[0] / N_COLS;   // 512
    dim3 grid(N_COLS / TILE, B);          // (4, 512)
    span_boost_kernel<<<grid, TPB>>>(scores, mask, gamma, wlog, out);
}

// round 3
// speedup vs baseline: 1.1889x; 1.0111x over previous
#include <cuda_runtime.h>

namespace {
constexpr int N_COLS = 8192;
constexpr int W_MAX  = 15;     // widths w = 2..15
constexpr int NW     = 14;
constexpr int HALO   = 14;     // W_MAX - 1
constexpr int TPB    = 128;
constexpr int K_TOK  = 16;     // tokens per thread
constexpr int TILE   = TPB * K_TOK;        // 2048
constexpr int LPAD   = 16;                 // left pad (>= HALO, 16-aligned)
constexpr int SV_PAD = 2080;               // TILE + LPAD + HALO rounded /4
constexpr float NEGV = -1.0e9f;
constexpr unsigned KEY_NINF = 0x007fffffu; // fkey(-inf)
}

// order-preserving float<->uint key (total order incl. -inf)
__device__ __forceinline__ unsigned fkey(float f) {
    int u = __float_as_int(f);
    return (u >= 0) ? ((unsigned)u | 0x80000000u) : ~(unsigned)u;
}
__device__ __forceinline__ float funkey(unsigned k) {
    unsigned u = (k & 0x80000000u) ? (k & 0x7fffffffu) : ~k;
    return __int_as_float((int)u);
}

__global__ __launch_bounds__(TPB, 6) void span_boost_kernel(
    const float* __restrict__ scores,
    const int*   __restrict__ mask,
    const float* __restrict__ gamma_p,
    const float* __restrict__ wlog,
    float*       __restrict__ out)
{
    __shared__ float    sv[SV_PAD];        // masked values; sv[i] = token col0-LPAD+i
    __shared__ float    sww[NW];
    __shared__ unsigned xb[HALO];          // CTA-left-halo boost (keyed max)
    __shared__ float    tailbuf[TPB][15];  // stride 15: conflict-free

    const float NINF = __int_as_float(0xff800000);
    const int   tid  = threadIdx.x;
    const int   row  = blockIdx.y;
    const int   col0 = blockIdx.x * TILE;
    const float* srow = scores + (size_t)row * N_COLS;
    const int*   mrow = mask   + (size_t)row * N_COLS;
    const int base_g = col0 - LPAD;

    // ---- stage masked tile (vectorized; scalar fallback at row edges) ----
    for (int i = tid * 4; i < SV_PAD; i += TPB * 4) {
        int g = base_g + i;
        float4 v;
        if (g >= 0 && g + 3 < N_COLS) {
            float4 s4 = *reinterpret_cast<const float4*>(srow + g);
            int4   m4 = *reinterpret_cast<const int4*>(mrow + g);
            v.x = (m4.x == 0) ? NEGV : s4.x;
            v.y = (m4.y == 0) ? NEGV : s4.y;
            v.z = (m4.z == 0) ? NEGV : s4.z;
            v.w = (m4.w == 0) ? NEGV : s4.w;
        } else {
            float t[4];
            #pragma unroll
            for (int k = 0; k < 4; k++) {
                int gg = g + k;
                t[k] = (gg >= 0 && gg < N_COLS)
                         ? ((mrow[gg] == 0) ? NEGV : srow[gg]) : NINF;
            }
            v.x = t[0]; v.y = t[1]; v.z = t[2]; v.w = t[3];
        }
        *reinterpret_cast<float4*>(sv + i) = v;
    }
    if (tid < HALO) xb[tid] = KEY_NINF;
    if (tid == 0) {  // softmax over 15 width logits
        float mx = wlog[0];
        #pragma unroll
        for (int j = 1; j < W_MAX; j++) mx = fmaxf(mx, wlog[j]);
        float e[W_MAX], ssum = 0.f;
        #pragma unroll
        for (int j = 0; j < W_MAX; j++) { e[j] = expf(wlog[j] - mx); ssum += e[j]; }
        float inv = 1.f / ssum;
        #pragma unroll
        for (int j = 0; j < NW; j++) sww[j] = e[j + 1] * inv;  // widths 2..15
    }
    __syncthreads();

    float ww[NW];
    #pragma unroll
    for (int j = 0; j < NW; j++) ww[j] = sww[j];

    const int base = LPAD + tid * K_TOK;   // sv index of this thread's token 0
    float r[K_TOK + HALO];
    float boost[K_TOK + HALO];

    // initial r window: r[12..29] (needed by start j=15; chunks 4-aligned)
    #pragma unroll
    for (int q = 3; q < 7; q++) {
        float4 f = *reinterpret_cast<const float4*>(&sv[base + 4 * q]);
        r[4*q+0] = f.x; r[4*q+1] = f.y; r[4*q+2] = f.z; r[4*q+3] = f.w;
    }
    {
        float2 f = *reinterpret_cast<const float2*>(&sv[base + 28]);
        r[28] = f.x; r[29] = f.y;
    }

    // ---- descending starts: incremental min, suffix-max scatter,
    //      streamed tail retirement. Token j first touched at step j (d=1,
    //      assignment); tail token j+14 last touched at step j (export). ----
    #pragma unroll
    for (int jj = 0; jj < K_TOK; jj++) {
        const int j = K_TOK - 1 - jj;      // 15 .. 0
        if (j == 11) {
            float4 f = *reinterpret_cast<const float4*>(&sv[base + 8]);
            r[8] = f.x; r[9] = f.y; r[10] = f.z; r[11] = f.w;
        }
        if (j == 7) {
            float4 f = *reinterpret_cast<const float4*>(&sv[base + 4]);
            r[4] = f.x; r[5] = f.y; r[6] = f.z; r[7] = f.w;
        }
        if (j == 3) {
            float4 f = *reinterpret_cast<const float4*>(&sv[base + 0]);
            r[0] = f.x; r[1] = f.y; r[2] = f.z; r[3] = f.w;
        }

        float mm[NW];
        float m = fminf(r[j], r[j + 1]);
        mm[0] = m;
        #pragma unroll
        for (int w = 3; w <= W_MAX; w++) { m = fminf(m, r[j + w - 1]); mm[w - 2] = m; }

        float g = ww[NW - 1] * mm[NW - 1];                 // d = 15
        if (j == K_TOK - 1) boost[j + 14] = g;
        else                boost[j + 14] = fmaxf(boost[j + 14], g);
        #pragma unroll
        for (int d = W_MAX - 1; d >= 2; d--) {             // d = 14..2
            g = fmaxf(g, ww[d - 2] * mm[d - 2]);
            if (j == K_TOK - 1) boost[j + d - 1] = g;
            else                boost[j + d - 1] = fmaxf(boost[j + d - 1], g);
        }
        boost[j] = g;                                      // d = 1 (first touch)

        if (j >= 2) tailbuf[tid][j - 2] = boost[j + 14];   // retire tail token
    }

    // ---- CTA-left halo starts: threads 0..13 compute start col0-14+h ----
    if (tid < HALO) {
        const int h = tid;                 // start at sv index h + 2
        float mm[NW];
        float m = fminf(sv[h + 2], sv[h + 3]);
        mm[0] = m;
        #pragma unroll
        for (int w = 3; w <= W_MAX; w++) { m = fminf(m, sv[h + 1 + w]); mm[w - 2] = m; }
        float g = ww[NW - 1] * mm[NW - 1];
        atomicMax(&xb[h], fkey(g));        // d = 15 -> token h
        #pragma unroll
        for (int d = W_MAX - 1; d >= 2; d--) {
            g = fmaxf(g, ww[d - 2] * mm[d - 2]);
            int i = h + d - W_MAX;
            if (i >= 0) atomicMax(&xb[i], fkey(g));
        }
    }
    __syncthreads();

    // ---- merge incoming contributions into tokens 0..13 ----
    if (tid > 0) {
        #pragma unroll
        for (int k = 0; k < HALO; k++)
            boost[k] = fmaxf(boost[k], tailbuf[tid - 1][k]);
    } else {
        #pragma unroll
        for (int k = 0; k < HALO; k++)
            boost[k] = fmaxf(boost[k], funkey(xb[k]));
    }

    // ---- epilogue: out = score + gamma * max(boost, masked) ----
    const float gamma = *gamma_p;
    const int tcol = col0 + tid * K_TOK;
    float* orow = out + (size_t)row * N_COLS;
    #pragma unroll
    for (int q = 0; q < K_TOK / 4; q++) {
        float4 s4 = *reinterpret_cast<const float4*>(&srow[tcol + 4 * q]);
        float4 o;
        o.x = s4.x + gamma * fmaxf(boost[4*q+0], sv[base + 4*q+0]);
        o.y = s4.y + gamma * fmaxf(boost[4*q+1], sv[base + 4*q+1]);
        o.z = s4.z + gamma * fmaxf(boost[4*q+2], sv[base + 4*q+2]);
        o.w = s4.w + gamma * fmaxf(boost[4*q+3], sv[base + 4*q+3]);
        *reinterpret_cast<float4*>(&orow[tcol + 4 * q]) = o;
    }
}

extern "C" void kernel_launch(void* const* d_in, const int* in_sizes, int n_in,
                              void* d_out, int out_size)
{
    const float* scores = (const float*)d_in[0];
    const int*   mask   = (const int*)d_in[1];
    const float* gamma  = (const float*)d_in[2];
    const float* wlog   = (const float*)d_in[3];
    float* out = (float*)d_out;
    const int B = in_sizes[0] / N_COLS;   // 512
    dim3 grid(N_COLS / TILE, B);          // (4, 512)
    span_boost_kernel<<<grid, TPB>>>(scores, mask, gamma, wlog, out);
}